// round 14
// baseline (speedup 1.0000x reference)
#include <cuda_runtime.h>
#include <cuda_fp16.h>
#include <cstddef>
#include <cstdint>

#define NNODES  100000
#define NEDGES  1600000
#define NGRAPHS 512
#define NFEAT   64
#define HID     128
#define NT      16

#define GEMM_BLKS 782            // ceil(100000/128)
#define FILL_BLKS 1024
#define SCAN_BLKS 98

// ---------------- static device scratch (zero-initialized at module load) ----------------
__device__ float  g_dinv[NNODES];
__device__ int    g_indeg[NNODES];        // invariant: zero at call entry (scan3 restores)
__device__ int    g_rowptr[NNODES + 1];
__device__ int    g_cursor[NNODES];       // zeroed by scan3 before fill
__device__ int    g_colidx[NEDGES];
__device__ int    g_bsum[128];
__device__ __half g_H[(size_t)NNODES * HID];
__device__ __half g_G[(size_t)NNODES * HID];
__device__ __half g_T[(size_t)NNODES * HID];

// ---------------- degree count (vectorized int4) ----------------
__global__ void k_count(const int* __restrict__ ei) {
    int i = blockIdx.x * blockDim.x + threadIdx.x;
    const int4* d4 = (const int4*)(ei + NEDGES);
    if (i < NEDGES / 4) {
        int4 v = d4[i];
        atomicAdd(&g_indeg[v.x], 1);
        atomicAdd(&g_indeg[v.y], 1);
        atomicAdd(&g_indeg[v.z], 1);
        atomicAdd(&g_indeg[v.w], 1);
    }
}

// ---------------- 3-pass exclusive scan of indeg -> rowptr (+ dinv) ----------------
__global__ void k_scan1() {
    __shared__ int s[1024];
    int i = blockIdx.x * 1024 + threadIdx.x;
    int v = (i < NNODES) ? g_indeg[i] : 0;
    if (i < NNODES) g_dinv[i] = rsqrtf((float)(v + 1));   // +1 self loop
    s[threadIdx.x] = v;
    for (int off = 1; off < 1024; off <<= 1) {
        __syncthreads();
        int t = (threadIdx.x >= off) ? s[threadIdx.x - off] : 0;
        __syncthreads();
        s[threadIdx.x] += t;
    }
    __syncthreads();
    if (i < NNODES) g_rowptr[i] = s[threadIdx.x] - v;
    if (threadIdx.x == 1023) g_bsum[blockIdx.x] = s[1023];
}

// parallel exclusive scan over the 98 block sums
__global__ void k_scan2() {
    __shared__ int s[128];
    int t = threadIdx.x;
    int v = (t < SCAN_BLKS) ? g_bsum[t] : 0;
    s[t] = v;
    for (int off = 1; off < 128; off <<= 1) {
        __syncthreads();
        int x = (t >= off) ? s[t - off] : 0;
        __syncthreads();
        s[t] += x;
    }
    __syncthreads();
    if (t < SCAN_BLKS) g_bsum[t] = s[t] - v;   // exclusive
}

// finalize rowptr; restore zero-invariant on indeg & cursor
__global__ void k_scan3() {
    int i = blockIdx.x * 1024 + threadIdx.x;
    if (i < NNODES) {
        g_rowptr[i] += g_bsum[blockIdx.x];
        g_cursor[i] = 0;
        g_indeg[i] = 0;
    }
    if (i == 0) g_rowptr[NNODES] = NEDGES;
}

// ---------------- tensor-core GEMM body: C[N,128] = A[N,K] @ W[K,128] ----------------
__device__ __forceinline__ void mma16816(float* c, const unsigned* a, unsigned b0, unsigned b1) {
    asm volatile(
        "mma.sync.aligned.m16n8k16.row.col.f32.f16.f16.f32 "
        "{%0,%1,%2,%3}, {%4,%5,%6,%7}, {%8,%9}, {%0,%1,%2,%3};"
        : "+f"(c[0]), "+f"(c[1]), "+f"(c[2]), "+f"(c[3])
        : "r"(a[0]), "r"(a[1]), "r"(a[2]), "r"(a[3]), "r"(b0), "r"(b1));
}

template <int K, int EPI, bool AHALF>
__device__ __forceinline__ void gemm_body(int bid, const void* __restrict__ Ain,
                                          const float* __restrict__ W,
                                          const float* __restrict__ bias,
                                          __half* __restrict__ C, __half* sm) {
    constexpr int PITCH = K + 8;
    __half* As = sm;                    // [128][PITCH]
    __half* Bs = sm + 128 * PITCH;      // [128][PITCH]  (W transposed: [n][k])

    int tid = threadIdx.x;
    int row0 = bid * 128;

    if (AHALF) {
        const uint4* A4 = (const uint4*)Ain;
        constexpr int CH = K / 8;
#pragma unroll
        for (int i = 0; i < 128 * CH / 256; i++) {
            int idx = tid + i * 256;
            int r = idx / CH, c = idx % CH;
            uint4 v = make_uint4(0u, 0u, 0u, 0u);
            if (row0 + r < NNODES) v = A4[(size_t)(row0 + r) * CH + c];
            *(uint4*)&As[r * PITCH + c * 8] = v;
        }
    } else {
        const float4* A4 = (const float4*)Ain;
        constexpr int CH = K / 4;
#pragma unroll
        for (int i = 0; i < 128 * CH / 256; i++) {
            int idx = tid + i * 256;
            int r = idx / CH, c = idx % CH;
            float4 v = make_float4(0.f, 0.f, 0.f, 0.f);
            if (row0 + r < NNODES) v = A4[(size_t)(row0 + r) * CH + c];
            __half2 p0 = __floats2half2_rn(v.x, v.y);
            __half2 p1 = __floats2half2_rn(v.z, v.w);
            uint2 u;
            u.x = *(unsigned*)&p0;
            u.y = *(unsigned*)&p1;
            *(uint2*)&As[r * PITCH + c * 4] = u;
        }
    }

    {   // W transpose: Bs[n][k] = W[k][n]
        int n = tid & 127;
        int kb = tid >> 7;
#pragma unroll
        for (int k2 = kb; k2 < K / 2; k2 += 2) {
            float a = W[(size_t)(2 * k2) * 128 + n];
            float b = W[(size_t)(2 * k2 + 1) * 128 + n];
            __half2 p = __floats2half2_rn(a, b);
            *reinterpret_cast<__half2*>(&Bs[n * PITCH + 2 * k2]) = p;
        }
    }
    __syncthreads();

    int wid = tid >> 5, lane = tid & 31;
    int gid = lane >> 2, tig = lane & 3;
    int m0 = (wid & 3) * 32;
    int n0 = (wid >> 2) * 64;

    float acc[2][8][4];
#pragma unroll
    for (int mt = 0; mt < 2; mt++)
#pragma unroll
        for (int nt = 0; nt < 8; nt++)
#pragma unroll
            for (int i = 0; i < 4; i++) acc[mt][nt][i] = 0.f;

#pragma unroll
    for (int k0 = 0; k0 < K; k0 += 16) {
        unsigned a[2][4];
#pragma unroll
        for (int mt = 0; mt < 2; mt++) {
            int r = m0 + mt * 16;
            a[mt][0] = *(const unsigned*)&As[(r + gid) * PITCH + k0 + 2 * tig];
            a[mt][1] = *(const unsigned*)&As[(r + gid + 8) * PITCH + k0 + 2 * tig];
            a[mt][2] = *(const unsigned*)&As[(r + gid) * PITCH + k0 + 2 * tig + 8];
            a[mt][3] = *(const unsigned*)&As[(r + gid + 8) * PITCH + k0 + 2 * tig + 8];
        }
#pragma unroll
        for (int nt = 0; nt < 8; nt++) {
            int n = n0 + nt * 8 + gid;
            unsigned b0 = *(const unsigned*)&Bs[n * PITCH + k0 + 2 * tig];
            unsigned b1 = *(const unsigned*)&Bs[n * PITCH + k0 + 2 * tig + 8];
            mma16816(acc[0][nt], a[0], b0, b1);
            mma16816(acc[1][nt], a[1], b0, b1);
        }
    }

#pragma unroll
    for (int mt = 0; mt < 2; mt++) {
        int r1 = row0 + m0 + mt * 16 + gid;
        int r2 = r1 + 8;
        float s1 = 1.f, s2 = 1.f;
        if (EPI == 0) {
            if (r1 < NNODES) s1 = g_dinv[r1];
            if (r2 < NNODES) s2 = g_dinv[r2];
        }
#pragma unroll
        for (int nt = 0; nt < 8; nt++) {
            int col = n0 + nt * 8 + 2 * tig;
            float v0 = acc[mt][nt][0], v1 = acc[mt][nt][1];
            float v2 = acc[mt][nt][2], v3 = acc[mt][nt][3];
            if (EPI == 0) { v0 *= s1; v1 *= s1; v2 *= s2; v3 *= s2; }
            else {
                float2 bb = *(const float2*)&bias[col];
                v0 = fmaxf(v0 + bb.x, 0.f); v1 = fmaxf(v1 + bb.y, 0.f);
                v2 = fmaxf(v2 + bb.x, 0.f); v3 = fmaxf(v3 + bb.y, 0.f);
            }
            if (r1 < NNODES) {
                __half2 p = __floats2half2_rn(v0, v1);
                *reinterpret_cast<__half2*>(&C[(size_t)r1 * 128 + col]) = p;
            }
            if (r2 < NNODES) {
                __half2 p = __floats2half2_rn(v2, v3);
                *reinterpret_cast<__half2*>(&C[(size_t)r2 * 128 + col]) = p;
            }
        }
    }
}

template <int K, int EPI, bool AHALF>
__global__ __launch_bounds__(256, 2) void k_gemm16(const void* __restrict__ Ain,
                                                   const float* __restrict__ W,
                                                   const float* __restrict__ bias,
                                                   __half* __restrict__ C) {
    extern __shared__ __half sm[];
    gemm_body<K, EPI, AHALF>(blockIdx.x, Ain, W, bias, C, sm);
}

// ---------------- mega: CSR fill (wave 1) | timeMLP gemm | layer1 gemm ----------------
__global__ __launch_bounds__(256, 2) void k_mega(const float* __restrict__ tein,
                                                 const float* __restrict__ Wt,
                                                 const float* __restrict__ bt,
                                                 const float* __restrict__ x,
                                                 const float* __restrict__ W1,
                                                 const int* __restrict__ ei) {
    extern __shared__ __half sm[];
    int b = blockIdx.x;
    if (b < FILL_BLKS) {
        int e0 = b * 256 + threadIdx.x;
#pragma unroll 2
        for (int e = e0; e < NEDGES; e += FILL_BLKS * 256) {
            int s = ei[e];
            int d = ei[NEDGES + e];
            int p = atomicAdd(&g_cursor[d], 1);
            g_colidx[g_rowptr[d] + p] = s;
        }
    } else if (b < FILL_BLKS + GEMM_BLKS) {
        gemm_body<128, 1, false>(b - FILL_BLKS, tein, Wt, bt, g_T, sm);
    } else {
        gemm_body<64, 0, false>(b - FILL_BLKS - GEMM_BLKS, x, W1, nullptr, g_G, sm);
    }
}

// ---------------- gather (r9 champion: 2 edges/step uint4, unroll 4) ----------------
__device__ __forceinline__ void addvec8(float* acc, uint4 v) {
    float2 f;
    f = __half22float2(*reinterpret_cast<__half2*>(&v.x)); acc[0] += f.x; acc[1] += f.y;
    f = __half22float2(*reinterpret_cast<__half2*>(&v.y)); acc[2] += f.x; acc[3] += f.y;
    f = __half22float2(*reinterpret_cast<__half2*>(&v.z)); acc[4] += f.x; acc[5] += f.y;
    f = __half22float2(*reinterpret_cast<__half2*>(&v.w)); acc[6] += f.x; acc[7] += f.y;
}

template <bool ADD_T>
__global__ __launch_bounds__(256, 6) void k_gather(const float* __restrict__ bias,
                                                   __half* __restrict__ Hout) {
    int w = (blockIdx.x * blockDim.x + threadIdx.x) >> 5;
    int lane = threadIdx.x & 31;
    if (w >= NNODES) return;
    int beg = g_rowptr[w], end = g_rowptr[w + 1];
    const uint4* G4 = (const uint4*)g_G;      // 16 uint4 per 128-feat row
    int hf = lane >> 4;                        // 0: even edges, 1: odd edges
    int fl = lane & 15;                        // 8-feature chunk id
    float acc[8];
#pragma unroll
    for (int i = 0; i < 8; i++) acc[i] = 0.f;

    for (int base = beg; base < end; base += 32) {
        int n = min(32, end - base);
        int myu = (lane < n) ? g_colidx[base + lane] : 0;
        int npair = n & ~1;
#pragma unroll 4
        for (int j = 0; j < npair; j += 2) {
            int u0 = __shfl_sync(0xffffffffu, myu, j);
            int u1 = __shfl_sync(0xffffffffu, myu, j + 1);
            int u = hf ? u1 : u0;
            uint4 v = G4[(size_t)u * 16 + fl];
            addvec8(acc, v);
        }
        if (npair < n) {
            int u0 = __shfl_sync(0xffffffffu, myu, npair);
            if (!hf) { uint4 v = G4[(size_t)u0 * 16 + fl]; addvec8(acc, v); }
        }
    }
    if (!hf) { uint4 v = G4[(size_t)w * 16 + fl]; addvec8(acc, v); }   // self term

#pragma unroll
    for (int i = 0; i < 8; i++) acc[i] += __shfl_xor_sync(0xffffffffu, acc[i], 16);

    if (!hf) {
        float d = g_dinv[w];
        float4 b0 = ((const float4*)bias)[fl * 2];
        float4 b1 = ((const float4*)bias)[fl * 2 + 1];
        float o[8];
        o[0] = fmaxf(d * acc[0] + b0.x, 0.f);
        o[1] = fmaxf(d * acc[1] + b0.y, 0.f);
        o[2] = fmaxf(d * acc[2] + b0.z, 0.f);
        o[3] = fmaxf(d * acc[3] + b0.w, 0.f);
        o[4] = fmaxf(d * acc[4] + b1.x, 0.f);
        o[5] = fmaxf(d * acc[5] + b1.y, 0.f);
        o[6] = fmaxf(d * acc[6] + b1.z, 0.f);
        o[7] = fmaxf(d * acc[7] + b1.w, 0.f);
        if (ADD_T) {
            uint4 t = ((const uint4*)g_T)[(size_t)w * 16 + fl];
            float2 f;
            f = __half22float2(*reinterpret_cast<__half2*>(&t.x)); o[0] += f.x; o[1] += f.y;
            f = __half22float2(*reinterpret_cast<__half2*>(&t.y)); o[2] += f.x; o[3] += f.y;
            f = __half22float2(*reinterpret_cast<__half2*>(&t.z)); o[4] += f.x; o[5] += f.y;
            f = __half22float2(*reinterpret_cast<__half2*>(&t.w)); o[6] += f.x; o[7] += f.y;
        }
        __half2 p0 = __floats2half2_rn(o[0], o[1]);
        __half2 p1 = __floats2half2_rn(o[2], o[3]);
        __half2 p2 = __floats2half2_rn(o[4], o[5]);
        __half2 p3 = __floats2half2_rn(o[6], o[7]);
        uint4 outv;
        outv.x = *(unsigned*)&p0; outv.y = *(unsigned*)&p1;
        outv.z = *(unsigned*)&p2; outv.w = *(unsigned*)&p3;
        ((uint4*)Hout)[(size_t)w * 16 + fl] = outv;
    }
}

// ---------------- fused pool + output head (atomics-free, one block per graph) ---------
// batch is sorted: graph g owns contiguous node range found by binary search.
__global__ __launch_bounds__(128) void k_poolout(const int* __restrict__ batch,
                                                 const __half* __restrict__ Hin,
                                                 const float* __restrict__ Wo,
                                                 const float* __restrict__ bo,
                                                 float* __restrict__ out) {
    __shared__ float sp[128];
    int g = blockIdx.x;
    int t = threadIdx.x;

    // lower_bound(batch, g) and lower_bound(batch, g+1)
    int lo = 0, hi = NNODES;
    while (lo < hi) { int m = (lo + hi) >> 1; if (batch[m] < g) lo = m + 1; else hi = m; }
    int start = lo;
    hi = NNODES;
    while (lo < hi) { int m = (lo + hi) >> 1; if (batch[m] < g + 1) lo = m + 1; else hi = m; }
    int end = lo;

    // thread t accumulates feature t over the graph's nodes (coalesced 256B rows)
    float s = 0.f;
    int v = start;
    for (; v + 4 <= end; v += 4) {
        __half h0 = Hin[(size_t)(v + 0) * 128 + t];
        __half h1 = Hin[(size_t)(v + 1) * 128 + t];
        __half h2 = Hin[(size_t)(v + 2) * 128 + t];
        __half h3 = Hin[(size_t)(v + 3) * 128 + t];
        s += __half2float(h0) + __half2float(h1) + __half2float(h2) + __half2float(h3);
    }
    for (; v < end; v++) s += __half2float(Hin[(size_t)v * 128 + t]);

    float inv = 1.f / fmaxf((float)(end - start), 1.f);
    sp[t] = s * inv;
    __syncthreads();

    if (t < NT) {
        float r = bo[t];
#pragma unroll 16
        for (int f = 0; f < 128; f++) r = fmaf(sp[f], Wo[f * NT + t], r);
        out[g * NT + t] = r;
    }
}

// ---------------- launch ----------------
extern "C" void kernel_launch(void* const* d_in, const int* in_sizes, int n_in,
                              void* d_out, int out_size) {
    (void)in_sizes; (void)n_in; (void)out_size;
    const float* x    = (const float*)d_in[0];
    const int*   ei   = (const int*)d_in[1];
    const float* tein = (const float*)d_in[2];
    const int*   bat  = (const int*)d_in[3];
    const float* Wt   = (const float*)d_in[4];
    const float* bt   = (const float*)d_in[5];
    const float* W1   = (const float*)d_in[6];
    const float* b1   = (const float*)d_in[7];
    const float* Ws   = (const float*)d_in[8];
    const float* bs   = (const float*)d_in[9];
    const float* Wo   = (const float*)d_in[10];
    const float* bo   = (const float*)d_in[11];
    float* out = (float*)d_out;

    __half *pG, *pH;
    cudaGetSymbolAddress((void**)&pG, g_G);
    cudaGetSymbolAddress((void**)&pH, g_H);

    const int GATH_BLKS = (NNODES * 32 + 255) / 256;
    const int SMEM128 = 2 * 128 * 136 * (int)sizeof(__half);  // 69632

    cudaFuncSetAttribute(k_mega, cudaFuncAttributeMaxDynamicSharedMemorySize, SMEM128);
    cudaFuncSetAttribute(k_gemm16<128, 0, true>,
                         cudaFuncAttributeMaxDynamicSharedMemorySize, SMEM128);

    // CSR: degree count -> 3-pass scan (+dinv, +zero invariants)
    k_count<<<(NEDGES / 4 + 255) / 256, 256>>>(ei);
    k_scan1<<<SCAN_BLKS, 1024>>>();
    k_scan2<<<1, 128>>>();
    k_scan3<<<SCAN_BLKS, 1024>>>();

    // concurrent: CSR fill (wave 1) | time-MLP gemm | layer1 gemm (G = dinv * xW1)
    k_mega<<<FILL_BLKS + 2 * GEMM_BLKS, 256, SMEM128>>>(tein, Wt, bt, x, W1, ei);

    // layer 1 aggregate
    k_gather<true><<<GATH_BLKS, 256>>>(b1, pH);

    // layer 2
    k_gemm16<128, 0, true><<<GEMM_BLKS, 256, SMEM128>>>(pH, Ws, nullptr, pG);
    k_gather<false><<<GATH_BLKS, 256>>>(bs, pH);

    // layer 3
    k_gemm16<128, 0, true><<<GEMM_BLKS, 256, SMEM128>>>(pH, Ws + 128 * 128, nullptr, pG);
    k_gather<false><<<GATH_BLKS, 256>>>(bs + 128, pH);

    // fused pool + head (atomics-free)
    k_poolout<<<NGRAPHS, 128>>>(bat, pH, Wo, bo, out);
}

// round 15
// speedup vs baseline: 1.0216x; 1.0216x over previous
#include <cuda_runtime.h>
#include <cuda_fp16.h>
#include <cstddef>
#include <cstdint>

#define NNODES  100000
#define NEDGES  1600000
#define NGRAPHS 512
#define NFEAT   64
#define HID     128
#define NT      16

#define GEMM_BLKS 782            // ceil(100000/128)
#define FILL_BLKS 1024
#define SCAN_BLKS 98

// ---------------- static device scratch (zero-initialized at module load) ----------------
__device__ float  g_dinv[NNODES];
__device__ int    g_indeg[NNODES];        // invariant: zero at call entry (scan3 restores)
__device__ int    g_rowptr[NNODES + 1];
__device__ int    g_cursor[NNODES];       // zeroed by scan3 before fill
__device__ int    g_colidx[NEDGES];
__device__ int    g_bsum[128];
__device__ __half g_H[(size_t)NNODES * HID];
__device__ __half g_G[(size_t)NNODES * HID];
__device__ __half g_T[(size_t)NNODES * HID];
__device__ float  g_pool[NGRAPHS * HID];  // invariant: zero at call entry (k_out restores)
__device__ float  g_cnt[NGRAPHS];         // invariant: zero at call entry (k_out restores)

// ---------------- degree count (vectorized int4) ----------------
__global__ void k_count(const int* __restrict__ ei) {
    int i = blockIdx.x * blockDim.x + threadIdx.x;
    const int4* d4 = (const int4*)(ei + NEDGES);
    if (i < NEDGES / 4) {
        int4 v = d4[i];
        atomicAdd(&g_indeg[v.x], 1);
        atomicAdd(&g_indeg[v.y], 1);
        atomicAdd(&g_indeg[v.z], 1);
        atomicAdd(&g_indeg[v.w], 1);
    }
}

// ---------------- 3-pass exclusive scan of indeg -> rowptr (+ dinv) ----------------
__global__ void k_scan1() {
    __shared__ int s[1024];
    int i = blockIdx.x * 1024 + threadIdx.x;
    int v = (i < NNODES) ? g_indeg[i] : 0;
    if (i < NNODES) g_dinv[i] = rsqrtf((float)(v + 1));   // +1 self loop
    s[threadIdx.x] = v;
    for (int off = 1; off < 1024; off <<= 1) {
        __syncthreads();
        int t = (threadIdx.x >= off) ? s[threadIdx.x - off] : 0;
        __syncthreads();
        s[threadIdx.x] += t;
    }
    __syncthreads();
    if (i < NNODES) g_rowptr[i] = s[threadIdx.x] - v;
    if (threadIdx.x == 1023) g_bsum[blockIdx.x] = s[1023];
}

// parallel exclusive scan over the 98 block sums
__global__ void k_scan2() {
    __shared__ int s[128];
    int t = threadIdx.x;
    int v = (t < SCAN_BLKS) ? g_bsum[t] : 0;
    s[t] = v;
    for (int off = 1; off < 128; off <<= 1) {
        __syncthreads();
        int x = (t >= off) ? s[t - off] : 0;
        __syncthreads();
        s[t] += x;
    }
    __syncthreads();
    if (t < SCAN_BLKS) g_bsum[t] = s[t] - v;   // exclusive
}

// finalize rowptr; restore zero-invariant on indeg & cursor
__global__ void k_scan3() {
    int i = blockIdx.x * 1024 + threadIdx.x;
    if (i < NNODES) {
        g_rowptr[i] += g_bsum[blockIdx.x];
        g_cursor[i] = 0;
        g_indeg[i] = 0;
    }
    if (i == 0) g_rowptr[NNODES] = NEDGES;
}

// ---------------- tensor-core GEMM body: C[N,128] = A[N,K] @ W[K,128] ----------------
__device__ __forceinline__ void mma16816(float* c, const unsigned* a, unsigned b0, unsigned b1) {
    asm volatile(
        "mma.sync.aligned.m16n8k16.row.col.f32.f16.f16.f32 "
        "{%0,%1,%2,%3}, {%4,%5,%6,%7}, {%8,%9}, {%0,%1,%2,%3};"
        : "+f"(c[0]), "+f"(c[1]), "+f"(c[2]), "+f"(c[3])
        : "r"(a[0]), "r"(a[1]), "r"(a[2]), "r"(a[3]), "r"(b0), "r"(b1));
}

__device__ __forceinline__ void ldsm_x4(unsigned* r, uint32_t addr) {
    asm volatile("ldmatrix.sync.aligned.m8n8.x4.shared.b16 {%0,%1,%2,%3}, [%4];"
        : "=r"(r[0]), "=r"(r[1]), "=r"(r[2]), "=r"(r[3]) : "r"(addr));
}
__device__ __forceinline__ void ldsm_x2(unsigned& r0, unsigned& r1, uint32_t addr) {
    asm volatile("ldmatrix.sync.aligned.m8n8.x2.shared.b16 {%0,%1}, [%2];"
        : "=r"(r0), "=r"(r1) : "r"(addr));
}

template <int K, int EPI, bool AHALF>
__device__ __forceinline__ void gemm_body(int bid, const void* __restrict__ Ain,
                                          const float* __restrict__ W,
                                          const float* __restrict__ bias,
                                          __half* __restrict__ C, __half* sm) {
    constexpr int PITCH = K + 8;
    __half* As = sm;                    // [128][PITCH]
    __half* Bs = sm + 128 * PITCH;      // [128][PITCH]  (W transposed: [n][k])

    int tid = threadIdx.x;
    int row0 = bid * 128;

    if (AHALF) {
        const uint4* A4 = (const uint4*)Ain;
        constexpr int CH = K / 8;
#pragma unroll
        for (int i = 0; i < 128 * CH / 256; i++) {
            int idx = tid + i * 256;
            int r = idx / CH, c = idx % CH;
            uint4 v = make_uint4(0u, 0u, 0u, 0u);
            if (row0 + r < NNODES) v = A4[(size_t)(row0 + r) * CH + c];
            *(uint4*)&As[r * PITCH + c * 8] = v;
        }
    } else {
        const float4* A4 = (const float4*)Ain;
        constexpr int CH = K / 4;
#pragma unroll
        for (int i = 0; i < 128 * CH / 256; i++) {
            int idx = tid + i * 256;
            int r = idx / CH, c = idx % CH;
            float4 v = make_float4(0.f, 0.f, 0.f, 0.f);
            if (row0 + r < NNODES) v = A4[(size_t)(row0 + r) * CH + c];
            __half2 p0 = __floats2half2_rn(v.x, v.y);
            __half2 p1 = __floats2half2_rn(v.z, v.w);
            uint2 u;
            u.x = *(unsigned*)&p0;
            u.y = *(unsigned*)&p1;
            *(uint2*)&As[r * PITCH + c * 4] = u;
        }
    }

    {   // W transpose: Bs[n][k] = W[k][n]
        int n = tid & 127;
        int kb = tid >> 7;
#pragma unroll
        for (int k2 = kb; k2 < K / 2; k2 += 2) {
            float a = W[(size_t)(2 * k2) * 128 + n];
            float b = W[(size_t)(2 * k2 + 1) * 128 + n];
            __half2 p = __floats2half2_rn(a, b);
            *reinterpret_cast<__half2*>(&Bs[n * PITCH + 2 * k2]) = p;
        }
    }
    __syncthreads();

    int wid = tid >> 5, lane = tid & 31;
    int gid = lane >> 2, tig = lane & 3;
    int m0 = (wid & 3) * 32;
    int n0 = (wid >> 2) * 64;

    // ldmatrix shared-space base addresses (bytes)
    uint32_t As_sh = (uint32_t)__cvta_generic_to_shared(As);
    uint32_t Bs_sh = (uint32_t)__cvta_generic_to_shared(Bs);
    // A x4: lanes 0-15 -> rows m+ (lane&15), col k0; lanes 16-31 -> same rows, col k0+8
    uint32_t addrA0 = As_sh + (uint32_t)(((m0 + (lane & 15)) * PITCH + ((lane >> 4) << 3)) * 2);
    uint32_t addrA1 = addrA0 + (uint32_t)(16 * PITCH * 2);
    // B x2: lanes 0-7 -> rows n0+(lane&7), col k0; lanes 8-15 -> col k0+8
    uint32_t addrB = Bs_sh + (uint32_t)(((n0 + (lane & 7)) * PITCH + (((lane >> 3) & 1) << 3)) * 2);

    float acc[2][8][4];
#pragma unroll
    for (int mt = 0; mt < 2; mt++)
#pragma unroll
        for (int nt = 0; nt < 8; nt++)
#pragma unroll
            for (int i = 0; i < 4; i++) acc[mt][nt][i] = 0.f;

#pragma unroll
    for (int k0 = 0; k0 < K; k0 += 16) {
        unsigned a[2][4];
        ldsm_x4(a[0], addrA0 + (uint32_t)(k0 * 2));
        ldsm_x4(a[1], addrA1 + (uint32_t)(k0 * 2));
#pragma unroll
        for (int nt = 0; nt < 8; nt++) {
            unsigned b0, b1;
            ldsm_x2(b0, b1, addrB + (uint32_t)((nt * 8 * PITCH + k0) * 2));
            mma16816(acc[0][nt], a[0], b0, b1);
            mma16816(acc[1][nt], a[1], b0, b1);
        }
    }

#pragma unroll
    for (int mt = 0; mt < 2; mt++) {
        int r1 = row0 + m0 + mt * 16 + gid;
        int r2 = r1 + 8;
        float s1 = 1.f, s2 = 1.f;
        if (EPI == 0) {
            if (r1 < NNODES) s1 = g_dinv[r1];
            if (r2 < NNODES) s2 = g_dinv[r2];
        }
#pragma unroll
        for (int nt = 0; nt < 8; nt++) {
            int col = n0 + nt * 8 + 2 * tig;
            float v0 = acc[mt][nt][0], v1 = acc[mt][nt][1];
            float v2 = acc[mt][nt][2], v3 = acc[mt][nt][3];
            if (EPI == 0) { v0 *= s1; v1 *= s1; v2 *= s2; v3 *= s2; }
            else {
                float2 bb = *(const float2*)&bias[col];
                v0 = fmaxf(v0 + bb.x, 0.f); v1 = fmaxf(v1 + bb.y, 0.f);
                v2 = fmaxf(v2 + bb.x, 0.f); v3 = fmaxf(v3 + bb.y, 0.f);
            }
            if (r1 < NNODES) {
                __half2 p = __floats2half2_rn(v0, v1);
                *reinterpret_cast<__half2*>(&C[(size_t)r1 * 128 + col]) = p;
            }
            if (r2 < NNODES) {
                __half2 p = __floats2half2_rn(v2, v3);
                *reinterpret_cast<__half2*>(&C[(size_t)r2 * 128 + col]) = p;
            }
        }
    }
}

template <int K, int EPI, bool AHALF>
__global__ __launch_bounds__(256, 2) void k_gemm16(const void* __restrict__ Ain,
                                                   const float* __restrict__ W,
                                                   const float* __restrict__ bias,
                                                   __half* __restrict__ C) {
    extern __shared__ __half sm[];
    gemm_body<K, EPI, AHALF>(blockIdx.x, Ain, W, bias, C, sm);
}

// ---------------- mega: CSR fill (wave 1) | timeMLP gemm | layer1 gemm ----------------
__global__ __launch_bounds__(256, 2) void k_mega(const float* __restrict__ tein,
                                                 const float* __restrict__ Wt,
                                                 const float* __restrict__ bt,
                                                 const float* __restrict__ x,
                                                 const float* __restrict__ W1,
                                                 const int* __restrict__ ei) {
    extern __shared__ __half sm[];
    int b = blockIdx.x;
    if (b < FILL_BLKS) {
        int e0 = b * 256 + threadIdx.x;
#pragma unroll 2
        for (int e = e0; e < NEDGES; e += FILL_BLKS * 256) {
            int s = ei[e];
            int d = ei[NEDGES + e];
            int p = atomicAdd(&g_cursor[d], 1);
            g_colidx[g_rowptr[d] + p] = s;
        }
    } else if (b < FILL_BLKS + GEMM_BLKS) {
        gemm_body<128, 1, false>(b - FILL_BLKS, tein, Wt, bt, g_T, sm);
    } else {
        gemm_body<64, 0, false>(b - FILL_BLKS - GEMM_BLKS, x, W1, nullptr, g_G, sm);
    }
}

// ---------------- gather (r9 champion: 2 edges/step uint4, unroll 4) ----------------
__device__ __forceinline__ void addvec8(float* acc, uint4 v) {
    float2 f;
    f = __half22float2(*reinterpret_cast<__half2*>(&v.x)); acc[0] += f.x; acc[1] += f.y;
    f = __half22float2(*reinterpret_cast<__half2*>(&v.y)); acc[2] += f.x; acc[3] += f.y;
    f = __half22float2(*reinterpret_cast<__half2*>(&v.z)); acc[4] += f.x; acc[5] += f.y;
    f = __half22float2(*reinterpret_cast<__half2*>(&v.w)); acc[6] += f.x; acc[7] += f.y;
}

template <bool ADD_T>
__global__ __launch_bounds__(256, 6) void k_gather(const float* __restrict__ bias,
                                                   __half* __restrict__ Hout) {
    int w = (blockIdx.x * blockDim.x + threadIdx.x) >> 5;
    int lane = threadIdx.x & 31;
    if (w >= NNODES) return;
    int beg = g_rowptr[w], end = g_rowptr[w + 1];
    const uint4* G4 = (const uint4*)g_G;      // 16 uint4 per 128-feat row
    int hf = lane >> 4;                        // 0: even edges, 1: odd edges
    int fl = lane & 15;                        // 8-feature chunk id
    float acc[8];
#pragma unroll
    for (int i = 0; i < 8; i++) acc[i] = 0.f;

    for (int base = beg; base < end; base += 32) {
        int n = min(32, end - base);
        int myu = (lane < n) ? g_colidx[base + lane] : 0;
        int npair = n & ~1;
#pragma unroll 4
        for (int j = 0; j < npair; j += 2) {
            int u0 = __shfl_sync(0xffffffffu, myu, j);
            int u1 = __shfl_sync(0xffffffffu, myu, j + 1);
            int u = hf ? u1 : u0;
            uint4 v = G4[(size_t)u * 16 + fl];
            addvec8(acc, v);
        }
        if (npair < n) {
            int u0 = __shfl_sync(0xffffffffu, myu, npair);
            if (!hf) { uint4 v = G4[(size_t)u0 * 16 + fl]; addvec8(acc, v); }
        }
    }
    if (!hf) { uint4 v = G4[(size_t)w * 16 + fl]; addvec8(acc, v); }   // self term

#pragma unroll
    for (int i = 0; i < 8; i++) acc[i] += __shfl_xor_sync(0xffffffffu, acc[i], 16);

    if (!hf) {
        float d = g_dinv[w];
        float4 b0 = ((const float4*)bias)[fl * 2];
        float4 b1 = ((const float4*)bias)[fl * 2 + 1];
        float o[8];
        o[0] = fmaxf(d * acc[0] + b0.x, 0.f);
        o[1] = fmaxf(d * acc[1] + b0.y, 0.f);
        o[2] = fmaxf(d * acc[2] + b0.z, 0.f);
        o[3] = fmaxf(d * acc[3] + b0.w, 0.f);
        o[4] = fmaxf(d * acc[4] + b1.x, 0.f);
        o[5] = fmaxf(d * acc[5] + b1.y, 0.f);
        o[6] = fmaxf(d * acc[6] + b1.z, 0.f);
        o[7] = fmaxf(d * acc[7] + b1.w, 0.f);
        if (ADD_T) {
            uint4 t = ((const uint4*)g_T)[(size_t)w * 16 + fl];
            float2 f;
            f = __half22float2(*reinterpret_cast<__half2*>(&t.x)); o[0] += f.x; o[1] += f.y;
            f = __half22float2(*reinterpret_cast<__half2*>(&t.y)); o[2] += f.x; o[3] += f.y;
            f = __half22float2(*reinterpret_cast<__half2*>(&t.z)); o[4] += f.x; o[5] += f.y;
            f = __half22float2(*reinterpret_cast<__half2*>(&t.w)); o[6] += f.x; o[7] += f.y;
        }
        __half2 p0 = __floats2half2_rn(o[0], o[1]);
        __half2 p1 = __floats2half2_rn(o[2], o[3]);
        __half2 p2 = __floats2half2_rn(o[4], o[5]);
        __half2 p3 = __floats2half2_rn(o[6], o[7]);
        uint4 outv;
        outv.x = *(unsigned*)&p0; outv.y = *(unsigned*)&p1;
        outv.z = *(unsigned*)&p2; outv.w = *(unsigned*)&p3;
        ((uint4*)Hout)[(size_t)w * 16 + fl] = outv;
    }
}

// ---------------- pool (batch sorted: accumulate runs, flush on change) ----------------
__global__ void k_pool(const int* __restrict__ batch, const __half* __restrict__ Hin) {
    int w = (blockIdx.x * blockDim.x + threadIdx.x) >> 5;
    int lane = threadIdx.x & 31;
    int v0 = w * 64;
    if (v0 >= NNODES) return;
    int v1 = min(v0 + 64, NNODES);
    const uint2* H2 = (const uint2*)Hin;
    int cur = batch[v0];
    float a0 = 0.f, a1 = 0.f, a2 = 0.f, a3 = 0.f;
    int cnt = 0;
    for (int v = v0; v < v1; v++) {
        int b = batch[v];
        if (b != cur) {
            atomicAdd(&g_pool[cur * 128 + lane * 4 + 0], a0);
            atomicAdd(&g_pool[cur * 128 + lane * 4 + 1], a1);
            atomicAdd(&g_pool[cur * 128 + lane * 4 + 2], a2);
            atomicAdd(&g_pool[cur * 128 + lane * 4 + 3], a3);
            if (lane == 0) atomicAdd(&g_cnt[cur], (float)cnt);
            cur = b; a0 = a1 = a2 = a3 = 0.f; cnt = 0;
        }
        uint2 h = H2[(size_t)v * 32 + lane];
        float2 f0 = __half22float2(*reinterpret_cast<__half2*>(&h.x));
        float2 f1 = __half22float2(*reinterpret_cast<__half2*>(&h.y));
        a0 += f0.x; a1 += f0.y; a2 += f1.x; a3 += f1.y;
        cnt++;
    }
    atomicAdd(&g_pool[cur * 128 + lane * 4 + 0], a0);
    atomicAdd(&g_pool[cur * 128 + lane * 4 + 1], a1);
    atomicAdd(&g_pool[cur * 128 + lane * 4 + 2], a2);
    atomicAdd(&g_pool[cur * 128 + lane * 4 + 3], a3);
    if (lane == 0) atomicAdd(&g_cnt[cur], (float)cnt);
}

// ---------------- output head (+ restore zero invariants) ----------------
__global__ void k_out(const float* __restrict__ Wo, const float* __restrict__ bo,
                      float* __restrict__ out) {
    __shared__ float sp[128];
    int g = blockIdx.x;
    int t = threadIdx.x;
    float c = g_cnt[g];
    float inv = 1.f / fmaxf(c, 1.f);
    sp[t] = g_pool[g * 128 + t] * inv;
    g_pool[g * 128 + t] = 0.f;          // restore invariant (own element)
    __syncthreads();
    if (t == 0) g_cnt[g] = 0.f;         // restore invariant
    if (t < NT) {
        float s = bo[t];
#pragma unroll 16
        for (int f = 0; f < 128; f++) s = fmaf(sp[f], Wo[f * NT + t], s);
        out[g * NT + t] = s;
    }
}

// ---------------- launch ----------------
extern "C" void kernel_launch(void* const* d_in, const int* in_sizes, int n_in,
                              void* d_out, int out_size) {
    (void)in_sizes; (void)n_in; (void)out_size;
    const float* x    = (const float*)d_in[0];
    const int*   ei   = (const int*)d_in[1];
    const float* tein = (const float*)d_in[2];
    const int*   bat  = (const int*)d_in[3];
    const float* Wt   = (const float*)d_in[4];
    const float* bt   = (const float*)d_in[5];
    const float* W1   = (const float*)d_in[6];
    const float* b1   = (const float*)d_in[7];
    const float* Ws   = (const float*)d_in[8];
    const float* bs   = (const float*)d_in[9];
    const float* Wo   = (const float*)d_in[10];
    const float* bo   = (const float*)d_in[11];
    float* out = (float*)d_out;

    __half *pG, *pH;
    cudaGetSymbolAddress((void**)&pG, g_G);
    cudaGetSymbolAddress((void**)&pH, g_H);

    const int GATH_BLKS = (NNODES * 32 + 255) / 256;
    const int POOL_WARPS = (NNODES + 63) / 64;
    const int POOL_BLKS = (POOL_WARPS * 32 + 255) / 256;
    const int SMEM128 = 2 * 128 * 136 * (int)sizeof(__half);  // 69632

    cudaFuncSetAttribute(k_mega, cudaFuncAttributeMaxDynamicSharedMemorySize, SMEM128);
    cudaFuncSetAttribute(k_gemm16<128, 0, true>,
                         cudaFuncAttributeMaxDynamicSharedMemorySize, SMEM128);

    // CSR: degree count -> 3-pass scan (+dinv, +zero invariants)
    k_count<<<(NEDGES / 4 + 255) / 256, 256>>>(ei);
    k_scan1<<<SCAN_BLKS, 1024>>>();
    k_scan2<<<1, 128>>>();
    k_scan3<<<SCAN_BLKS, 1024>>>();

    // concurrent: CSR fill (wave 1) | time-MLP gemm | layer1 gemm (G = dinv * xW1)
    k_mega<<<FILL_BLKS + 2 * GEMM_BLKS, 256, SMEM128>>>(tein, Wt, bt, x, W1, ei);

    // layer 1 aggregate
    k_gather<true><<<GATH_BLKS, 256>>>(b1, pH);

    // layer 2
    k_gemm16<128, 0, true><<<GEMM_BLKS, 256, SMEM128>>>(pH, Ws, nullptr, pG);
    k_gather<false><<<GATH_BLKS, 256>>>(bs, pH);

    // layer 3
    k_gemm16<128, 0, true><<<GEMM_BLKS, 256, SMEM128>>>(pH, Ws + 128 * 128, nullptr, pG);
    k_gather<false><<<GATH_BLKS, 256>>>(bs + 128, pH);

    // pool + head
    k_pool<<<POOL_BLKS, 256>>>(bat, pH);
    k_out<<<NGRAPHS, 128>>>(Wo, bo, out);
}